// round 15
// baseline (speedup 1.0000x reference)
#include <cuda_runtime.h>
#include <cstdint>

#define B_DIM 256
#define N_DIM 64
#define T_DIM 4096
#define H_DIM 16
#define TS    256   // t-tile per CTA
#define CH    64    // t-chunk width (4 chunks per tile)
#define SBC   72    // x chunk SMEM row stride (floats): mod 32 = 8 -> conflict-free
#define SW    68    // w SMEM row stride (floats), overlaid on chunk-3 buffer

// Scratch (device global — no allocation allowed)
__device__ float g_energy[B_DIM * N_DIM];

// ======================= helpers =======================
__device__ __forceinline__ uint32_t smem_u32(const void* p) {
    uint32_t a;
    asm("{ .reg .u64 t; cvta.to.shared.u64 t, %1; cvt.u32.u64 %0, t; }" : "=r"(a) : "l"(p));
    return a;
}
__device__ __forceinline__ void cp16(uint32_t smem_dst, const void* gsrc) {
    asm volatile("cp.async.cg.shared.global [%0], [%1], 16;" :: "r"(smem_dst), "l"(gsrc) : "memory");
}
#define CP_COMMIT() asm volatile("cp.async.commit_group;" ::: "memory")
#define CP_WAIT(n)  asm volatile("cp.async.wait_group %0;" :: "n"(n) : "memory")

__device__ __forceinline__ uint32_t f2tf32(float f) {
    uint32_t r;
    asm("cvt.rna.tf32.f32 %0, %1;" : "=r"(r) : "f"(f));
    return r;
}
__device__ __forceinline__ void mma_tf32(float& d0, float& d1, float& d2, float& d3,
                                         uint32_t a0, uint32_t a1, uint32_t a2, uint32_t a3,
                                         uint32_t b0, uint32_t b1) {
    asm volatile(
        "mma.sync.aligned.m16n8k8.row.col.f32.tf32.tf32.f32 "
        "{%0,%1,%2,%3},{%4,%5,%6,%7},{%8,%9},{%0,%1,%2,%3};"
        : "+f"(d0), "+f"(d1), "+f"(d2), "+f"(d3)
        : "r"(a0), "r"(a1), "r"(a2), "r"(a3), "r"(b0), "r"(b1));
}

// ---------------------------------------------------------------------------
// Kernel 1: energy[b,n] = var(x[b,n,:]) over T. One warp per (b,n) row.
// ---------------------------------------------------------------------------
__global__ __launch_bounds__(256) void energy_kernel(const float* __restrict__ x) {
    int gw   = (blockIdx.x * blockDim.x + threadIdx.x) >> 5;
    int lane = threadIdx.x & 31;
    if (gw >= B_DIM * N_DIM) return;
    const float4* row = reinterpret_cast<const float4*>(x + (size_t)gw * T_DIM);
    float s = 0.f, ss = 0.f;
#pragma unroll
    for (int k = 0; k < 32; k++) {
        float4 v = row[k * 32 + lane];
        s  += (v.x + v.y) + (v.z + v.w);
        ss += v.x * v.x + v.y * v.y + v.z * v.z + v.w * v.w;
    }
#pragma unroll
    for (int o = 16; o > 0; o >>= 1) {
        s  += __shfl_xor_sync(0xffffffffu, s, o);
        ss += __shfl_xor_sync(0xffffffffu, ss, o);
    }
    if (lane == 0) {
        float m = s * (1.f / T_DIM);
        g_energy[gw] = fmaf(-m, m, ss * (1.f / T_DIM));
    }
}

// ---------------------------------------------------------------------------
// Kernel 2: attn weights (rank-1 logits + softmax) -> attn_out [b][i][j].
// ---------------------------------------------------------------------------
__global__ __launch_bounds__(64) void attn_kernel(const float* __restrict__ Wq,
                                                  const float* __restrict__ bq,
                                                  const float* __restrict__ Wk,
                                                  const float* __restrict__ bk,
                                                  float* __restrict__ attn_out) {
    __shared__ float e[N_DIM];
    __shared__ float wsm[N_DIM * 65];
    int b = blockIdx.x;
    int i = threadIdx.x;
    e[i] = g_energy[b * N_DIM + i];

    float c0 = 0.f, c1 = 0.f, c2 = 0.f, c3 = 0.f;
#pragma unroll
    for (int h = 0; h < H_DIM; h++) {
        float wq = Wq[h], bqh = bq[h], wk = Wk[h], bkh = bk[h];
        c0 = fmaf(wq, wk, c0);
        c1 = fmaf(wq, bkh, c1);
        c2 = fmaf(bqh, wk, c2);
        c3 = fmaf(bqh, bkh, c3);
    }
    __syncthreads();

    const float scale = 0.25f;
    float ei = e[i];
    float l[N_DIM];
    float mx = -1e30f;
#pragma unroll
    for (int j = 0; j < N_DIM; j++) {
        float ej = e[j];
        float v = scale * (ei * ej * c0 + ei * c1 + ej * c2 + c3);
        if (j == i) v = -1e9f;
        l[j] = v;
        mx = fmaxf(mx, v);
    }
    float sum = 0.f;
#pragma unroll
    for (int j = 0; j < N_DIM; j++) {
        float w = __expf(l[j] - mx);
        l[j] = w;
        sum += w;
    }
    float inv = 1.f / sum;
#pragma unroll
    for (int j = 0; j < N_DIM; j++)
        wsm[i * 65 + j] = l[j] * inv;
    __syncthreads();

    float* ao = attn_out + (size_t)b * N_DIM * N_DIM;
#pragma unroll
    for (int k = 0; k < N_DIM; k++)
        ao[k * 64 + i] = wsm[k * 65 + i];  // w[k][i], coalesced
}

// ---------------------------------------------------------------------------
// Kernel 3: out[b,i,t] = sum_j w[b,i,j]*x[b,j,t] + x[b,i,t]
// 3 CTAs/SM: SMEM = 4 chunk buffers only (72 KB); w is loaded into chunk-3's
// buffer first, A fragments built from it, then chunk 3 cp.async'd OVER it.
// Inner loop identical to R6: 8 warps = 2 i-halves x 4 t-quarters, dual
// accumulator chains, B frags raw fp32 bits (tf32 HW truncation), exact fp32
// residual. Reverse batch order for L2 tail reuse. regs capped at 84.
// ---------------------------------------------------------------------------
__global__ __launch_bounds__(256, 3) void out_kernel(const float* __restrict__ x,
                                                     const float* __restrict__ w,
                                                     float* __restrict__ out) {
    extern __shared__ float smem[];
    float* xs = smem;                       // 4 x [64][SBC]; buf3 doubles as ws
    float* ws = smem + 3 * N_DIM * SBC;     // [64][SW] overlay on buf3

    int b    = B_DIM - 1 - (int)blockIdx.y;  // reverse batch order (L2 reuse)
    int tile = blockIdx.x;
    int tid  = threadIdx.x;
    int wid  = tid >> 5;
    int lane = tid & 31;

    const float* xb = x + (size_t)b * N_DIM * T_DIM + (size_t)tile * TS;
    const float* wsrc = w + (size_t)b * N_DIM * N_DIM;

    // Group 0: w into buf3 (1024 float4, 4 per thread, 16 float4/row).
#pragma unroll
    for (int k = 0; k < 4; k++) {
        int f  = k * 256 + tid;
        int i  = f >> 4;
        int c4 = f & 15;
        cp16(smem_u32(ws + i * SW + c4 * 4), wsrc + f * 4);
    }
    CP_COMMIT();
    // Groups 1..3: chunks 0..2.
#pragma unroll
    for (int ch = 0; ch < 3; ch++) {
        float* xc = xs + ch * N_DIM * SBC;
#pragma unroll
        for (int k = 0; k < 4; k++) {
            int f  = k * 256 + tid;
            int j  = f >> 4;
            int c4 = f & 15;
            cp16(smem_u32(xc + j * SBC + c4 * 4),
                 xb + (size_t)j * T_DIM + ch * CH + c4 * 4);
        }
        CP_COMMIT();
    }

    int ih = wid & 1;          // i half: rows [ih*32, +32)
    int tq = wid >> 1;         // t quarter within chunk: [tq*16, +16)
    int i0 = ih * 32;
    int r  = lane >> 2;        // 0..7
    int c  = lane & 3;         // 0..3

    // Wait for w (chunks 0-2 may still be in flight), build A fragments.
    CP_WAIT(3);
    __syncthreads();
    uint32_t a[2][8][4];
#pragma unroll
    for (int band = 0; band < 2; band++) {
        int ib = i0 + band * 16;
#pragma unroll
        for (int ks = 0; ks < 8; ks++) {
            int j0 = ks * 8 + c;
            a[band][ks][0] = f2tf32(ws[(ib + r) * SW + j0]);
            a[band][ks][1] = f2tf32(ws[(ib + r + 8) * SW + j0]);
            a[band][ks][2] = f2tf32(ws[(ib + r) * SW + j0 + 4]);
            a[band][ks][3] = f2tf32(ws[(ib + r + 8) * SW + j0 + 4]);
        }
    }
    __syncthreads();   // everyone done reading ws (buf3)

    // Group 4: chunk 3 over buf3.
    {
        float* xc = xs + 3 * N_DIM * SBC;
#pragma unroll
        for (int k = 0; k < 4; k++) {
            int f  = k * 256 + tid;
            int j  = f >> 4;
            int c4 = f & 15;
            cp16(smem_u32(xc + j * SBC + c4 * 4),
                 xb + (size_t)j * T_DIM + 3 * CH + c4 * 4);
        }
        CP_COMMIT();
    }

    float* ob = out + (size_t)b * N_DIM * T_DIM + (size_t)tile * TS;

    // Pending after commit of chunk3: {g1,g2,g3,g4} -> waits 3/2/1/0.
#pragma unroll
    for (int ch = 0; ch < 4; ch++) {
        if (ch == 0) CP_WAIT(3);
        else if (ch == 1) CP_WAIT(2);
        else if (ch == 2) CP_WAIT(1);
        else CP_WAIT(0);
        __syncthreads();

        const float* xc = xs + ch * N_DIM * SBC;
#pragma unroll
        for (int nt = 0; nt < 2; nt++) {
            int t0 = tq * 16 + nt * 8;
            float d[2][4];
#pragma unroll
            for (int band = 0; band < 2; band++)
#pragma unroll
                for (int q = 0; q < 4; q++) d[band][q] = 0.f;
#pragma unroll
            for (int ks = 0; ks < 8; ks++) {
                // Raw fp32 bits -> tf32 truncation in HW.
                uint32_t b0 = __float_as_uint(xc[(ks * 8 + c) * SBC + t0 + r]);
                uint32_t b1 = __float_as_uint(xc[(ks * 8 + c + 4) * SBC + t0 + r]);
                mma_tf32(d[0][0], d[0][1], d[0][2], d[0][3],
                         a[0][ks][0], a[0][ks][1], a[0][ks][2], a[0][ks][3], b0, b1);
                mma_tf32(d[1][0], d[1][1], d[1][2], d[1][3],
                         a[1][ks][0], a[1][ks][1], a[1][ks][2], a[1][ks][3], b0, b1);
            }
            // Epilogue: exact fp32 residual + coalesced STG.64.
            int tcol = t0 + 2 * c;
#pragma unroll
            for (int band = 0; band < 2; band++) {
                int row0 = i0 + band * 16 + r, row1 = row0 + 8;
                float2 res0 = *reinterpret_cast<const float2*>(xc + row0 * SBC + tcol);
                float2 res1 = *reinterpret_cast<const float2*>(xc + row1 * SBC + tcol);
                float2 o0 = make_float2(d[band][0] + res0.x, d[band][1] + res0.y);
                float2 o1 = make_float2(d[band][2] + res1.x, d[band][3] + res1.y);
                int tg = ch * CH + tcol;
                *reinterpret_cast<float2*>(ob + (size_t)row0 * T_DIM + tg) = o0;
                *reinterpret_cast<float2*>(ob + (size_t)row1 * T_DIM + tg) = o1;
            }
        }
    }
}

extern "C" void kernel_launch(void* const* d_in, const int* in_sizes, int n_in,
                              void* d_out, int out_size) {
    const float* x  = (const float*)d_in[0];
    const float* Wq = (const float*)d_in[1];
    const float* bq = (const float*)d_in[2];
    const float* Wk = (const float*)d_in[3];
    const float* bk = (const float*)d_in[4];

    float* out = (float*)d_out;
    float* attn_out = out + (size_t)B_DIM * N_DIM * T_DIM;

    const int smem_bytes = 4 * N_DIM * SBC * (int)sizeof(float);  // 73728
    cudaFuncSetAttribute(out_kernel, cudaFuncAttributeMaxDynamicSharedMemorySize, smem_bytes);

    energy_kernel<<<(B_DIM * N_DIM * 32) / 256, 256>>>(x);
    attn_kernel<<<B_DIM, 64>>>(Wq, bq, Wk, bk, attn_out);
    dim3 grid(T_DIM / TS, B_DIM);
    out_kernel<<<grid, 256, smem_bytes>>>(x, attn_out, out);
}

// round 16
// speedup vs baseline: 1.2683x; 1.2683x over previous
#include <cuda_runtime.h>
#include <cstdint>

#define B_DIM 256
#define N_DIM 64
#define T_DIM 4096
#define H_DIM 16
#define TS    256   // t-tile per CTA
#define CH    64    // t-chunk width (4 chunks per tile)
#define SBC   72    // x chunk SMEM row stride (floats): mod 32 = 8 -> conflict-free
#define SW    68    // w SMEM row stride (floats), overlaid on chunk-3 buffer

// Scratch (device global — no allocation allowed)
__device__ float g_energy[B_DIM * N_DIM];

// ======================= helpers =======================
__device__ __forceinline__ uint32_t smem_u32(const void* p) {
    uint32_t a;
    asm("{ .reg .u64 t; cvta.to.shared.u64 t, %1; cvt.u32.u64 %0, t; }" : "=r"(a) : "l"(p));
    return a;
}
__device__ __forceinline__ void cp16(uint32_t smem_dst, const void* gsrc) {
    asm volatile("cp.async.cg.shared.global [%0], [%1], 16;" :: "r"(smem_dst), "l"(gsrc) : "memory");
}
#define CP_COMMIT() asm volatile("cp.async.commit_group;" ::: "memory")
#define CP_WAIT(n)  asm volatile("cp.async.wait_group %0;" :: "n"(n) : "memory")

__device__ __forceinline__ uint32_t f2tf32(float f) {
    uint32_t r;
    asm("cvt.rna.tf32.f32 %0, %1;" : "=r"(r) : "f"(f));
    return r;
}
__device__ __forceinline__ void mma_tf32(float& d0, float& d1, float& d2, float& d3,
                                         uint32_t a0, uint32_t a1, uint32_t a2, uint32_t a3,
                                         uint32_t b0, uint32_t b1) {
    asm volatile(
        "mma.sync.aligned.m16n8k8.row.col.f32.tf32.tf32.f32 "
        "{%0,%1,%2,%3},{%4,%5,%6,%7},{%8,%9},{%0,%1,%2,%3};"
        : "+f"(d0), "+f"(d1), "+f"(d2), "+f"(d3)
        : "r"(a0), "r"(a1), "r"(a2), "r"(a3), "r"(b0), "r"(b1));
}

// ---------------------------------------------------------------------------
// Kernel 1: energy[b,n] = var(x[b,n,:]) over T. One warp per (b,n) row.
// ---------------------------------------------------------------------------
__global__ __launch_bounds__(256) void energy_kernel(const float* __restrict__ x) {
    int gw   = (blockIdx.x * blockDim.x + threadIdx.x) >> 5;
    int lane = threadIdx.x & 31;
    if (gw >= B_DIM * N_DIM) return;
    const float4* row = reinterpret_cast<const float4*>(x + (size_t)gw * T_DIM);
    float s = 0.f, ss = 0.f;
#pragma unroll
    for (int k = 0; k < 32; k++) {
        float4 v = row[k * 32 + lane];
        s  += (v.x + v.y) + (v.z + v.w);
        ss += v.x * v.x + v.y * v.y + v.z * v.z + v.w * v.w;
    }
#pragma unroll
    for (int o = 16; o > 0; o >>= 1) {
        s  += __shfl_xor_sync(0xffffffffu, s, o);
        ss += __shfl_xor_sync(0xffffffffu, ss, o);
    }
    if (lane == 0) {
        float m = s * (1.f / T_DIM);
        g_energy[gw] = fmaf(-m, m, ss * (1.f / T_DIM));
    }
}

// ---------------------------------------------------------------------------
// Kernel 2: attn weights (rank-1 logits + softmax) -> attn_out [b][i][j].
// ---------------------------------------------------------------------------
__global__ __launch_bounds__(64) void attn_kernel(const float* __restrict__ Wq,
                                                  const float* __restrict__ bq,
                                                  const float* __restrict__ Wk,
                                                  const float* __restrict__ bk,
                                                  float* __restrict__ attn_out) {
    __shared__ float e[N_DIM];
    __shared__ float wsm[N_DIM * 65];
    int b = blockIdx.x;
    int i = threadIdx.x;
    e[i] = g_energy[b * N_DIM + i];

    float c0 = 0.f, c1 = 0.f, c2 = 0.f, c3 = 0.f;
#pragma unroll
    for (int h = 0; h < H_DIM; h++) {
        float wq = Wq[h], bqh = bq[h], wk = Wk[h], bkh = bk[h];
        c0 = fmaf(wq, wk, c0);
        c1 = fmaf(wq, bkh, c1);
        c2 = fmaf(bqh, wk, c2);
        c3 = fmaf(bqh, bkh, c3);
    }
    __syncthreads();

    const float scale = 0.25f;
    float ei = e[i];
    float l[N_DIM];
    float mx = -1e30f;
#pragma unroll
    for (int j = 0; j < N_DIM; j++) {
        float ej = e[j];
        float v = scale * (ei * ej * c0 + ei * c1 + ej * c2 + c3);
        if (j == i) v = -1e9f;
        l[j] = v;
        mx = fmaxf(mx, v);
    }
    float sum = 0.f;
#pragma unroll
    for (int j = 0; j < N_DIM; j++) {
        float w = __expf(l[j] - mx);
        l[j] = w;
        sum += w;
    }
    float inv = 1.f / sum;
#pragma unroll
    for (int j = 0; j < N_DIM; j++)
        wsm[i * 65 + j] = l[j] * inv;
    __syncthreads();

    float* ao = attn_out + (size_t)b * N_DIM * N_DIM;
#pragma unroll
    for (int k = 0; k < N_DIM; k++)
        ao[k * 64 + i] = wsm[k * 65 + i];  // w[k][i], coalesced
}

// ---------------------------------------------------------------------------
// Kernel 3: out[b,i,t] = sum_j w[b,i,j]*x[b,j,t] + x[b,i,t]
// 3 CTAs/SM: SMEM = 4 chunk buffers (72 KB); w loaded into buf3 first,
// A fragments (ONE 16-row band per warp = 32 regs) built from it, then
// chunk 3 cp.async'd over it. Dual independent MMA chains recovered by
// processing two t-positions (tA, tA+8) per inner loop sharing A. 8 warps =
// 4 i-bands x 2 t-halves. B frags raw fp32 bits (tf32 HW truncation);
// residual exact fp32. Reverse batch order for L2 tail reuse.
// ---------------------------------------------------------------------------
__global__ __launch_bounds__(256, 3) void out_kernel(const float* __restrict__ x,
                                                     const float* __restrict__ w,
                                                     float* __restrict__ out) {
    extern __shared__ float smem[];
    float* xs = smem;                       // 4 x [64][SBC]; buf3 doubles as ws
    float* ws = smem + 3 * N_DIM * SBC;     // [64][SW] overlay on buf3

    int b    = B_DIM - 1 - (int)blockIdx.y;  // reverse batch order (L2 reuse)
    int tile = blockIdx.x;
    int tid  = threadIdx.x;
    int wid  = tid >> 5;
    int lane = tid & 31;

    const float* xb = x + (size_t)b * N_DIM * T_DIM + (size_t)tile * TS;
    const float* wsrc = w + (size_t)b * N_DIM * N_DIM;

    // Group 0: w into buf3 (1024 float4, 4 per thread, 16 float4/row).
#pragma unroll
    for (int k = 0; k < 4; k++) {
        int f  = k * 256 + tid;
        int i  = f >> 4;
        int c4 = f & 15;
        cp16(smem_u32(ws + i * SW + c4 * 4), wsrc + f * 4);
    }
    CP_COMMIT();
    // Groups 1..3: chunks 0..2.
#pragma unroll
    for (int ch = 0; ch < 3; ch++) {
        float* xc = xs + ch * N_DIM * SBC;
#pragma unroll
        for (int k = 0; k < 4; k++) {
            int f  = k * 256 + tid;
            int j  = f >> 4;
            int c4 = f & 15;
            cp16(smem_u32(xc + j * SBC + c4 * 4),
                 xb + (size_t)j * T_DIM + ch * CH + c4 * 4);
        }
        CP_COMMIT();
    }

    int i0 = (wid & 3) * 16;   // i band (16 rows)
    int th = wid >> 2;         // t half: [th*32, +32) within chunk
    int r  = lane >> 2;        // 0..7
    int c  = lane & 3;         // 0..3

    // Wait for w only (chunks 0-2 still in flight), build A fragments.
    CP_WAIT(3);
    __syncthreads();
    uint32_t a[8][4];
#pragma unroll
    for (int ks = 0; ks < 8; ks++) {
        int j0 = ks * 8 + c;
        a[ks][0] = f2tf32(ws[(i0 + r) * SW + j0]);
        a[ks][1] = f2tf32(ws[(i0 + r + 8) * SW + j0]);
        a[ks][2] = f2tf32(ws[(i0 + r) * SW + j0 + 4]);
        a[ks][3] = f2tf32(ws[(i0 + r + 8) * SW + j0 + 4]);
    }
    __syncthreads();   // everyone done reading ws (buf3)

    // Group 4: chunk 3 over buf3.
    {
        float* xc = xs + 3 * N_DIM * SBC;
#pragma unroll
        for (int k = 0; k < 4; k++) {
            int f  = k * 256 + tid;
            int j  = f >> 4;
            int c4 = f & 15;
            cp16(smem_u32(xc + j * SBC + c4 * 4),
                 xb + (size_t)j * T_DIM + 3 * CH + c4 * 4);
        }
        CP_COMMIT();
    }

    float* ob = out + (size_t)b * N_DIM * T_DIM + (size_t)tile * TS;

    // Pending after commit of chunk3: {g1,g2,g3,g4} -> waits 3/2/1/0.
#pragma unroll
    for (int ch = 0; ch < 4; ch++) {
        if (ch == 0) CP_WAIT(3);
        else if (ch == 1) CP_WAIT(2);
        else if (ch == 2) CP_WAIT(1);
        else CP_WAIT(0);
        __syncthreads();

        const float* xc = xs + ch * N_DIM * SBC;
#pragma unroll
        for (int pz = 0; pz < 2; pz++) {
            int tA = th * 32 + pz * 16;   // two t-positions share A frags
            int tB = tA + 8;
            float dA0 = 0.f, dA1 = 0.f, dA2 = 0.f, dA3 = 0.f;
            float dB0 = 0.f, dB1 = 0.f, dB2 = 0.f, dB3 = 0.f;
#pragma unroll
            for (int ks = 0; ks < 8; ks++) {
                const float* xr0 = xc + (ks * 8 + c) * SBC;
                const float* xr1 = xc + (ks * 8 + c + 4) * SBC;
                // Raw fp32 bits -> tf32 truncation in HW.
                uint32_t b0A = __float_as_uint(xr0[tA + r]);
                uint32_t b1A = __float_as_uint(xr1[tA + r]);
                uint32_t b0B = __float_as_uint(xr0[tB + r]);
                uint32_t b1B = __float_as_uint(xr1[tB + r]);
                mma_tf32(dA0, dA1, dA2, dA3,
                         a[ks][0], a[ks][1], a[ks][2], a[ks][3], b0A, b1A);
                mma_tf32(dB0, dB1, dB2, dB3,
                         a[ks][0], a[ks][1], a[ks][2], a[ks][3], b0B, b1B);
            }
            // Epilogue: exact fp32 residual + coalesced STG.64 (x2 positions).
            int row0 = i0 + r, row1 = row0 + 8;
            int tcA = tA + 2 * c, tcB = tB + 2 * c;
            float2 rA0 = *reinterpret_cast<const float2*>(xc + row0 * SBC + tcA);
            float2 rA1 = *reinterpret_cast<const float2*>(xc + row1 * SBC + tcA);
            float2 rB0 = *reinterpret_cast<const float2*>(xc + row0 * SBC + tcB);
            float2 rB1 = *reinterpret_cast<const float2*>(xc + row1 * SBC + tcB);
            float2 oA0 = make_float2(dA0 + rA0.x, dA1 + rA0.y);
            float2 oA1 = make_float2(dA2 + rA1.x, dA3 + rA1.y);
            float2 oB0 = make_float2(dB0 + rB0.x, dB1 + rB0.y);
            float2 oB1 = make_float2(dB2 + rB1.x, dB3 + rB1.y);
            int gA = ch * CH + tcA, gB = ch * CH + tcB;
            *reinterpret_cast<float2*>(ob + (size_t)row0 * T_DIM + gA) = oA0;
            *reinterpret_cast<float2*>(ob + (size_t)row1 * T_DIM + gA) = oA1;
            *reinterpret_cast<float2*>(ob + (size_t)row0 * T_DIM + gB) = oB0;
            *reinterpret_cast<float2*>(ob + (size_t)row1 * T_DIM + gB) = oB1;
        }
    }
}

extern "C" void kernel_launch(void* const* d_in, const int* in_sizes, int n_in,
                              void* d_out, int out_size) {
    const float* x  = (const float*)d_in[0];
    const float* Wq = (const float*)d_in[1];
    const float* bq = (const float*)d_in[2];
    const float* Wk = (const float*)d_in[3];
    const float* bk = (const float*)d_in[4];

    float* out = (float*)d_out;
    float* attn_out = out + (size_t)B_DIM * N_DIM * T_DIM;

    const int smem_bytes = 4 * N_DIM * SBC * (int)sizeof(float);  // 73728
    cudaFuncSetAttribute(out_kernel, cudaFuncAttributeMaxDynamicSharedMemorySize, smem_bytes);

    energy_kernel<<<(B_DIM * N_DIM * 32) / 256, 256>>>(x);
    attn_kernel<<<B_DIM, 64>>>(Wq, bq, Wk, bk, attn_out);
    dim3 grid(T_DIM / TS, B_DIM);
    out_kernel<<<grid, 256, smem_bytes>>>(x, attn_out, out);
}